// round 2
// baseline (speedup 1.0000x reference)
#include <cuda_runtime.h>
#include <cstdint>

#define HD   512
#define BT   32768            // B*T = 128*256
#define BSZ  128
#define KBM  4096             // 128*32 attention rows per idx
#define KBTOT 32768

// ---------------- scratch (device globals; no allocations allowed) ----------
__device__ float g_bufA[BT * HD];
__device__ float g_bufB[BT * HD];
__device__ float g_arn [BT * HD];
__device__ float g_add [BT * HD];
__device__ float g_E   [6 * KBM * HD];
__device__ float g_u   [6 * KBM];      // [idx][b*32+r]
__device__ float g_eng [BT];
__device__ int   g_maskmode;           // 0=uint8, 1=int32, 2=float32

typedef unsigned long long u64;

__device__ __forceinline__ u64 pack2(float lo, float hi) {
    u64 r; asm("mov.b64 %0,{%1,%2};" : "=l"(r) : "f"(lo), "f"(hi)); return r;
}
__device__ __forceinline__ void fma2(u64& d, u64 a, u64 b) {
    asm("fma.rn.f32x2 %0,%1,%2,%0;" : "+l"(d) : "l"(a), "l"(b));
}
__device__ __forceinline__ float2 unpack2(u64 v) {
    float lo, hi; asm("mov.b64 {%0,%1},%2;" : "=f"(lo), "=f"(hi) : "l"(v));
    return make_float2(lo, hi);
}

__device__ __forceinline__ float actf(float v, int act) {
    if (act == 1) return fmaxf(v, 0.0f);
    if (act == 2) return 1.0f / (1.0f + expf(-v));
    if (act == 3) return tanhf(v);
    return v;
}

// Dual-source loads: logical K axis is [0, Ksplit) from src0 (row width Ksplit)
// and [Ksplit, K) from src1 (row width K1).
__device__ __forceinline__ float4 ldA(const float* __restrict__ A0,
                                      const float* __restrict__ A1,
                                      int a1shift, int Ksplit, int K1,
                                      int row, int kg) {
    if (kg < Ksplit) return *(const float4*)(A0 + (size_t)row * Ksplit + kg);
    return *(const float4*)(A1 + (size_t)(row >> a1shift) * K1 + (kg - Ksplit));
}
__device__ __forceinline__ float4 ldB(const float* __restrict__ B0,
                                      const float* __restrict__ B1,
                                      int Ksplit, int N, int kg, int col) {
    if (kg < Ksplit) return *(const float4*)(B0 + (size_t)kg * N + col);
    return *(const float4*)(B1 + (size_t)(kg - Ksplit) * N + col);
}

// ---------------- SGEMM: C[M,N] = act(A @ B + bias), fp32, f32x2 inner ------
// 128x128 block tile, 256 threads, 8x8 per thread, K-tile 8, double-buffered.
__global__ __launch_bounds__(256, 2)
void sgemm_f32x2(const float* __restrict__ A0, const float* __restrict__ A1,
                 int a1shift,
                 const float* __restrict__ B0, const float* __restrict__ B1,
                 const float* __restrict__ bias,
                 float* __restrict__ C,
                 int M, int N, int K, int Ksplit,
                 int act, int finalMode,
                 const float* __restrict__ p_arn, const float* __restrict__ p_add,
                 const float* __restrict__ p_cell, const float* __restrict__ p_eng,
                 float* __restrict__ outH, float* __restrict__ outC) {
    __shared__ float As[2][8][132];
    __shared__ float Bs[2][8][132];

    const int tid   = threadIdx.x;
    const int mBase = blockIdx.y * 128;
    const int nBase = blockIdx.x * 128;
    const int K1    = K - Ksplit;

    const int am = tid >> 1;            // 0..127 (A row within tile)
    const int ak = (tid & 1) << 2;      // 0 or 4 (A k sub-chunk)
    const int bk = tid >> 5;            // 0..7  (B k row)
    const int bn = (tid & 31) << 2;     // 0..124 (B col chunk)

    const int tm = (tid >> 4) << 3;     // 0..120
    const int tn = (tid & 15) << 3;     // 0..120

    u64 acc[8][4];
#pragma unroll
    for (int i = 0; i < 8; i++)
#pragma unroll
        for (int j = 0; j < 4; j++) acc[i][j] = 0ull;

    const int nk = K >> 3;

    // prologue: tile 0 -> stage 0
    {
        float4 av = ldA(A0, A1, a1shift, Ksplit, K1, mBase + am, ak);
        float4 bv = ldB(B0, B1, Ksplit, N, bk, nBase + bn);
        As[0][ak + 0][am] = av.x; As[0][ak + 1][am] = av.y;
        As[0][ak + 2][am] = av.z; As[0][ak + 3][am] = av.w;
        *(float4*)&Bs[0][bk][bn] = bv;
    }
    __syncthreads();

    int s = 0;
    for (int kt = 0; kt < nk; kt++) {
        float4 av, bv;
        const bool more = (kt + 1 < nk);
        if (more) {
            const int kg = (kt + 1) << 3;
            av = ldA(A0, A1, a1shift, Ksplit, K1, mBase + am, kg + ak);
            bv = ldB(B0, B1, Ksplit, N, kg + bk, nBase + bn);
        }
#pragma unroll
        for (int kk = 0; kk < 8; kk++) {
            float4 a0 = *(const float4*)&As[s][kk][tm];
            float4 a1 = *(const float4*)&As[s][kk][tm + 4];
            float4 b0 = *(const float4*)&Bs[s][kk][tn];
            float4 b1 = *(const float4*)&Bs[s][kk][tn + 4];
            u64 bb[4];
            bb[0] = pack2(b0.x, b0.y); bb[1] = pack2(b0.z, b0.w);
            bb[2] = pack2(b1.x, b1.y); bb[3] = pack2(b1.z, b1.w);
            float aa[8] = {a0.x, a0.y, a0.z, a0.w, a1.x, a1.y, a1.z, a1.w};
#pragma unroll
            for (int i = 0; i < 8; i++) {
                u64 a2 = pack2(aa[i], aa[i]);
                fma2(acc[i][0], a2, bb[0]);
                fma2(acc[i][1], a2, bb[1]);
                fma2(acc[i][2], a2, bb[2]);
                fma2(acc[i][3], a2, bb[3]);
            }
        }
        if (more) {
            const int ns = s ^ 1;
            As[ns][ak + 0][am] = av.x; As[ns][ak + 1][am] = av.y;
            As[ns][ak + 2][am] = av.z; As[ns][ak + 3][am] = av.w;
            *(float4*)&Bs[ns][bk][bn] = bv;
            __syncthreads();
            s = ns;
        }
    }

    // epilogue
#pragma unroll
    for (int i = 0; i < 8; i++) {
        const int row = mBase + tm + i;
        const size_t cro = (size_t)row * N;
#pragma unroll
        for (int j2 = 0; j2 < 4; j2++) {
            float2 v = unpack2(acc[i][j2]);
            const int col = nBase + tn + (j2 << 1);
            float x0 = v.x, x1 = v.y;
            if (bias) { x0 += bias[col]; x1 += bias[col + 1]; }
            x0 = actf(x0, act);
            x1 = actf(x1, act);
            if (finalMode) {
                const float e = p_eng[row];
                const size_t i0 = cro + col, i1 = i0 + 1;
                float ni0 = p_arn[i0] * p_add[i0];
                float ni1 = p_arn[i1] * p_add[i1];
                float uc0 = p_cell[i0] + ni0 * e;
                float uc1 = p_cell[i1] + ni1 * e;
                outC[i0] = uc0; outC[i1] = uc1;
                outH[i0] = x0 * tanhf(uc0);
                outH[i1] = x1 * tanhf(uc1);
            } else {
                C[cro + col]     = x0;
                C[cro + col + 1] = x1;
            }
        }
    }
}

// u[idx][m] = sum_n E[idx*4096+m][n] * v_att[idx][n]; one warp per row
__global__ void u_reduce_kernel(const float* __restrict__ E,
                                const float* __restrict__ v_att,
                                float* __restrict__ u) {
    const int row  = blockIdx.x * 8 + (threadIdx.x >> 5);
    const int lane = threadIdx.x & 31;
    const int idx  = row >> 12;  // row / 4096
    const float* e = E + (size_t)row * HD;
    const float* v = v_att + idx * HD;
    float sacc = 0.0f;
#pragma unroll 4
    for (int k = lane; k < HD; k += 32) sacc += e[k] * v[k];
#pragma unroll
    for (int o = 16; o; o >>= 1) sacc += __shfl_down_sync(0xffffffffu, sacc, o);
    if (!lane) u[row] = sacc;
}

// eng[row] = dot(cell[row], eng_w)
__global__ void eng_kernel(const float* __restrict__ cell,
                           const float* __restrict__ w,
                           float* __restrict__ eng) {
    const int row  = blockIdx.x * 8 + (threadIdx.x >> 5);
    const int lane = threadIdx.x & 31;
    const float* c = cell + (size_t)row * HD;
    float sacc = 0.0f;
#pragma unroll 4
    for (int k = lane; k < HD; k += 32) sacc += c[k] * w[k];
#pragma unroll
    for (int o = 16; o; o >>= 1) sacc += __shfl_down_sync(0xffffffffu, sacc, o);
    if (!lane) eng[row] = sacc;
}

// Detect the storage dtype of kb_mask (bools may arrive as uint8 / int32 /
// float32 depending on harness conversion). Scans the first 64K 32-bit words
// (256 KB — safe for every candidate layout; smallest possible buffer is 4 MB).
//   any word == 0x3F800000 (1.0f)          -> float32
//   else any word > 1                      -> packed uint8 bools
//   else                                   -> int32 0/1
__global__ void detect_mask_kernel(const unsigned int* __restrict__ w) {
    __shared__ int sF, sG;
    if (threadIdx.x == 0) { sF = 0; sG = 0; }
    __syncthreads();
    int f = 0, g = 0;
    for (int i = threadIdx.x; i < 65536; i += blockDim.x) {
        const unsigned int v = w[i];
        if (v == 0x3F800000u) f = 1;
        else if (v > 1u) g = 1;
    }
    if (f) atomicOr(&sF, 1);
    if (g) atomicOr(&sG, 1);
    __syncthreads();
    if (threadIdx.x == 0) g_maskmode = sF ? 2 : (sG ? 0 : 1);
}

// u_t_k[b][j] = mask ? 0 : sum_d S_d[digit_d(j)], S_d = sum over hops of u
__global__ void utk_kernel(const float* __restrict__ u,
                           const void* __restrict__ maskraw,
                           float* __restrict__ out) {
    __shared__ float S[3][32];
    const int b = blockIdx.y;
    if (threadIdx.x < 96) {
        const int d = threadIdx.x >> 5, i = threadIdx.x & 31;
        S[d][i] = u[(0 * 3 + d) * KBM + b * 32 + i]
                + u[(1 * 3 + d) * KBM + b * 32 + i];
    }
    __syncthreads();
    const int mode = g_maskmode;
    const int j = blockIdx.x * 256 + threadIdx.x;
    const float v = S[0][j >> 10] + S[1][(j >> 5) & 31] + S[2][j & 31];
    const size_t o = (size_t)b * KBTOT + j;
    bool m;
    if (mode == 0)      m = ((const unsigned char*)maskraw)[o] != 0;
    else if (mode == 1) m = ((const int*)maskraw)[o] != 0;
    else                m = ((const float*)maskraw)[o] != 0.0f;
    out[o] = m ? 0.0f : v;
}

extern "C" void kernel_launch(void* const* d_in, const int* in_sizes, int n_in,
                              void* d_out, int out_size) {
    const float* query   = (const float*)d_in[0];
    const float* kb_keys = (const float*)d_in[1];
    const float* Wq      = (const float*)d_in[2];
    const float* Wk      = (const float*)d_in[3];
    const float* v_att   = (const float*)d_in[4];
    const float* x       = (const float*)d_in[5];
    const float* hidden  = (const float*)d_in[6];
    const float* cell    = (const float*)d_in[7];
    const float* arn_w1  = (const float*)d_in[8];
    const float* arn_b1  = (const float*)d_in[9];
    const float* arn_w2  = (const float*)d_in[10];
    const float* arn_b2  = (const float*)d_in[11];
    const float* arn_w3  = (const float*)d_in[12];
    const float* arn_b3  = (const float*)d_in[13];
    const float* add_w1  = (const float*)d_in[14];
    const float* add_b1  = (const float*)d_in[15];
    const float* add_w2  = (const float*)d_in[16];
    const float* add_b2  = (const float*)d_in[17];
    const float* add_w3  = (const float*)d_in[18];
    const float* add_b3  = (const float*)d_in[19];
    const float* eng_w   = (const float*)d_in[20];
    const float* wc_w1   = (const float*)d_in[21];
    const float* wc_b1   = (const float*)d_in[22];
    const float* wc_w2   = (const float*)d_in[23];
    const float* wc_b2   = (const float*)d_in[24];
    const float* wc_w3   = (const float*)d_in[25];
    const float* wc_b3   = (const float*)d_in[26];
    const float* wc_w4   = (const float*)d_in[27];
    const float* wc_b4   = (const float*)d_in[28];
    const void*  kb_mask = d_in[29];

    float* out     = (float*)d_out;
    float* out_utk = out;                       // 128*32768
    float* outH    = out + (size_t)BSZ * KBTOT; // 128*256*512
    float* outC    = outH + (size_t)BT * HD;

    float *bufA, *bufB, *arnp, *addp, *Ep, *up, *engp;
    cudaGetSymbolAddress((void**)&bufA, g_bufA);
    cudaGetSymbolAddress((void**)&bufB, g_bufB);
    cudaGetSymbolAddress((void**)&arnp, g_arn);
    cudaGetSymbolAddress((void**)&addp, g_add);
    cudaGetSymbolAddress((void**)&Ep,   g_E);
    cudaGetSymbolAddress((void**)&up,   g_u);
    cudaGetSymbolAddress((void**)&engp, g_eng);

    const dim3 blk(256);
    const dim3 gAtt(HD / 128, KBM / 128);   // (4, 32)
    const dim3 gMlp(HD / 128, BT / 128);    // (4, 256)

    detect_mask_kernel<<<1, 1024>>>((const unsigned int*)kb_mask);

    // ---- attention: E[idx] = tanh([kb_keys[dim] | query(bcast)] @ [Wk;Wq]) ----
    for (int idx = 0; idx < 6; idx++) {
        const int dim = idx % 3;
        sgemm_f32x2<<<gAtt, blk>>>(
            kb_keys + (size_t)dim * KBM * HD, query, /*a1shift=*/5,
            Wk + (size_t)idx * HD * HD, Wq + (size_t)idx * HD * HD,
            nullptr, Ep + (size_t)idx * KBM * HD,
            KBM, HD, 2 * HD, HD, /*act=tanh*/3, 0,
            nullptr, nullptr, nullptr, nullptr, nullptr, nullptr);
    }
    u_reduce_kernel<<<6 * KBM / 8, 256>>>(Ep, v_att, up);
    {
        dim3 g(KBTOT / 256, BSZ);
        utk_kernel<<<g, 256>>>(up, kb_mask, out_utk);
    }

    // ---- eng = cell @ eng_w ----
    eng_kernel<<<BT / 8, 256>>>(cell, eng_w, engp);

    // ---- arn path ----
    sgemm_f32x2<<<gMlp, blk>>>(x, hidden, 0, arn_w1, arn_w1 + HD * HD, arn_b1,
                               bufA, BT, HD, 2 * HD, HD, 1, 0,
                               nullptr, nullptr, nullptr, nullptr, nullptr, nullptr);
    sgemm_f32x2<<<gMlp, blk>>>(bufA, bufA, 0, arn_w2, arn_w2, arn_b2,
                               bufB, BT, HD, HD, HD, 1, 0,
                               nullptr, nullptr, nullptr, nullptr, nullptr, nullptr);
    sgemm_f32x2<<<gMlp, blk>>>(bufB, bufB, 0, arn_w3, arn_w3, arn_b3,
                               arnp, BT, HD, HD, HD, 2, 0,
                               nullptr, nullptr, nullptr, nullptr, nullptr, nullptr);

    // ---- add path ----
    sgemm_f32x2<<<gMlp, blk>>>(x, hidden, 0, add_w1, add_w1 + HD * HD, add_b1,
                               bufA, BT, HD, 2 * HD, HD, 1, 0,
                               nullptr, nullptr, nullptr, nullptr, nullptr, nullptr);
    sgemm_f32x2<<<gMlp, blk>>>(bufA, bufA, 0, add_w2, add_w2, add_b2,
                               bufB, BT, HD, HD, HD, 1, 0,
                               nullptr, nullptr, nullptr, nullptr, nullptr, nullptr);
    sgemm_f32x2<<<gMlp, blk>>>(bufB, bufB, 0, add_w3, add_w3, add_b3,
                               addp, BT, HD, HD, HD, 3, 0,
                               nullptr, nullptr, nullptr, nullptr, nullptr, nullptr);

    // ---- wc path (final GEMM fuses the cell/hidden update epilogue) ----
    sgemm_f32x2<<<gMlp, blk>>>(x, hidden, 0, wc_w1, wc_w1 + HD * HD, wc_b1,
                               bufA, BT, HD, 2 * HD, HD, 1, 0,
                               nullptr, nullptr, nullptr, nullptr, nullptr, nullptr);
    sgemm_f32x2<<<gMlp, blk>>>(bufA, bufA, 0, wc_w2, wc_w2, wc_b2,
                               bufB, BT, HD, HD, HD, 1, 0,
                               nullptr, nullptr, nullptr, nullptr, nullptr, nullptr);
    sgemm_f32x2<<<gMlp, blk>>>(bufB, bufB, 0, wc_w3, wc_w3, wc_b3,
                               bufA, BT, HD, HD, HD, 1, 0,
                               nullptr, nullptr, nullptr, nullptr, nullptr, nullptr);
    sgemm_f32x2<<<gMlp, blk>>>(bufA, bufA, 0, wc_w4, wc_w4, wc_b4,
                               bufB /*unused*/, BT, HD, HD, HD, 2, /*final*/1,
                               arnp, addp, cell, engp, outH, outC);
}